// round 6
// baseline (speedup 1.0000x reference)
#include <cuda_runtime.h>

#define HID 50
#define GCAP 16384
#define NMAX_ELEMS 50000000
#define ASTR 101
#define WSTR 52
#define TILE 128

// ---------------- scratch (device globals; no allocations) ----------------
__device__ float  g_x[NMAX_ELEMS];
__device__ float  g_mean[(size_t)GCAP * HID];
__device__ float  g_invc[GCAP];
__device__ int    g_cnt[GCAP];
__device__ double g_sum[64];
__device__ double g_sq[64];
__device__ float  g_scale[64];
__device__ float  g_shift[64];

// ---------------- small utility kernels ----------------
__global__ void zero_cnt_k() {
    int i = blockIdx.x * blockDim.x + threadIdx.x;
    if (i < GCAP) g_cnt[i] = 0;
}

__global__ void count_k(const int* __restrict__ seg, int N) {
    int i = blockIdx.x * blockDim.x + threadIdx.x;
    if (i < N) atomicAdd(&g_cnt[seg[i]], 1);
}

__global__ void invc_k() {
    int i = blockIdx.x * blockDim.x + threadIdx.x;
    if (i < GCAP) {
        int c = g_cnt[i];
        g_invc[i] = 1.0f / (float)(c > 1 ? c : 1);
    }
}

__global__ void zero_stats_k() {
    int i = blockIdx.x * blockDim.x + threadIdx.x;
    if (i < GCAP * HID) g_mean[i] = 0.f;
    if (i < 64) { g_sum[i] = 0.0; g_sq[i] = 0.0; }
}

// segment sum into g_mean; h computed on the fly.
// mode 0: h = xy @ w_init + b_init ; mode 1: h = g_x * scale + shift
__global__ void segsum_k(int mode, const float* __restrict__ xy,
                         const int* __restrict__ seg,
                         const float* __restrict__ WI, const float* __restrict__ BI,
                         int N) {
    __shared__ int ss[256];
    __shared__ float sxy[512];
    int base = blockIdx.x * 256;
    int cnt = N - base; if (cnt > 256) cnt = 256;
    if (cnt <= 0) return;
    for (int i = threadIdx.x; i < cnt; i += 64) ss[i] = seg[base + i];
    if (mode == 0)
        for (int i = threadIdx.x; i < 2 * cnt; i += 64) sxy[i] = xy[2 * base + i];
    __syncthreads();
    int f = threadIdx.x;
    if (f >= HID) return;
    float w0 = 0.f, w1 = 0.f, bf = 0.f, sc = 0.f, sh = 0.f;
    if (mode == 0) { w0 = WI[f]; w1 = WI[HID + f]; bf = BI[f]; }
    else           { sc = g_scale[f]; sh = g_shift[f]; }
    float acc = 0.f;
    int cur = ss[0];
    #pragma unroll 4
    for (int i = 0; i < cnt; i++) {
        float v;
        if (mode == 0) v = fmaf(sxy[2 * i], w0, fmaf(sxy[2 * i + 1], w1, bf));
        else           v = fmaf(g_x[(size_t)(base + i) * HID + f], sc, sh);
        int s = ss[i];
        if (s != cur) {
            atomicAdd(&g_mean[(size_t)cur * HID + f], acc);
            acc = 0.f; cur = s;
        }
        acc += v;
    }
    atomicAdd(&g_mean[(size_t)cur * HID + f], acc);
}

// ---------------- fused MLP + BN-stats kernel (float4 weight loads) ----------------
__global__ __launch_bounds__(128)
void mlp_k(int mode, const float* __restrict__ xy, const int* __restrict__ seg,
           const float* __restrict__ WI, const float* __restrict__ BI,
           const float* __restrict__ W1, const float* __restrict__ B1,
           const float* __restrict__ W2, const float* __restrict__ B2,
           int N) {
    extern __shared__ float sm[];
    float* s_w1  = sm;                     // 100 x 52 = 5200
    float* s_w   = s_w1 + 5200;            // 4 x 50 x 52 = 10400
    float* s_b1  = s_w + 10400;            // 52
    float* s_b2  = s_b1 + 52;              // 4 x 52 = 208
    float* s_wi  = s_b2 + 208;             // 152
    float* s_sum = s_wi + 152;             // 52
    float* s_sq  = s_sum + 52;             // 52
    int*   s_seg = (int*)(s_sq + 52);      // 128
    float* act   = (float*)(s_seg + 128);  // 128 x 101 = 12928
    // total floats: 16244 + 12928 = 29172 -> 116,688 bytes

    int tid = threadIdx.x;
    // zero padded weight region (cols 50,51 of every 52-wide row must be 0)
    for (int i = tid; i < 15600; i += 128) sm[i] = 0.f;
    __syncthreads();
    for (int i = tid; i < 5000; i += 128)  { int r = i / 50, c = i - r * 50; s_w1[r * WSTR + c] = W1[i]; }
    for (int i = tid; i < 10000; i += 128) { int r = i / 50, c = i - r * 50; s_w[r * WSTR + c] = W2[i]; }
    if (tid < 52) s_b1[tid] = (tid < 50) ? B1[tid] : 0.f;
    for (int i = tid; i < 208; i += 128) { int l = i / 52, c = i - l * 52; s_b2[i] = (c < 50) ? B2[l * 50 + c] : 0.f; }
    for (int i = tid; i < 152; i += 128) s_wi[i] = (i < 100) ? WI[i] : ((i < 150) ? BI[i - 100] : 0.f);
    if (tid < 52) { s_sum[tid] = 0.f; s_sq[tid] = 0.f; }

    int base = blockIdx.x * TILE;
    int cnt = N - base; if (cnt > TILE) cnt = TILE;
    if (cnt < 0) cnt = 0;
    if (tid < cnt) s_seg[tid] = seg[base + tid];
    __syncthreads();

    // stage h into cols [50,100)
    for (int idx = tid; idx < cnt * HID; idx += 128) {
        int n = idx / 50, f = idx - n * 50;
        float hv;
        if (mode == 0) {
            float x0 = __ldg(&xy[2 * (base + n)]);
            float x1 = __ldg(&xy[2 * (base + n) + 1]);
            hv = fmaf(x0, s_wi[f], fmaf(x1, s_wi[50 + f], s_wi[100 + f]));
        } else {
            hv = fmaf(g_x[(size_t)base * HID + idx], g_scale[f], g_shift[f]);
        }
        act[n * ASTR + 50 + f] = hv;
    }
    // stage glob into cols [0,50) (thread-per-node; sorted ids -> L1 broadcast)
    if (tid < cnt) {
        int s = s_seg[tid];
        float ic = g_invc[s];
        const float* mrow = &g_mean[(size_t)s * HID];
        float* arow = act + tid * ASTR;
        #pragma unroll 1
        for (int f = 0; f < HID; f++) arow[f] = mrow[f] * ic;
    }
    __syncthreads();

    float acc[52];
    bool valid = tid < cnt;
    if (valid) {
        float* row = act + tid * ASTR;
        // layer 1: 100 -> 50, relu
        #pragma unroll
        for (int j = 0; j < 52; j++) acc[j] = s_b1[j];
        #pragma unroll 1
        for (int k = 0; k < 100; k++) {
            float xk = row[k];
            const float4* w = (const float4*)(s_w1 + k * WSTR);
            #pragma unroll
            for (int p = 0; p < 13; p++) {
                float4 wv = w[p];
                acc[4 * p]     = fmaf(xk, wv.x, acc[4 * p]);
                acc[4 * p + 1] = fmaf(xk, wv.y, acc[4 * p + 1]);
                acc[4 * p + 2] = fmaf(xk, wv.z, acc[4 * p + 2]);
                acc[4 * p + 3] = fmaf(xk, wv.w, acc[4 * p + 3]);
            }
        }
        #pragma unroll
        for (int j = 0; j < HID; j++) row[j] = fmaxf(acc[j], 0.f);
        // layers 2..5: 50 -> 50, relu on first 3
        #pragma unroll 1
        for (int l = 0; l < 4; l++) {
            const float* wl = s_w + l * 2600;
            const float* bl = s_b2 + l * 52;
            #pragma unroll
            for (int j = 0; j < 52; j++) acc[j] = bl[j];
            #pragma unroll 1
            for (int k = 0; k < 50; k++) {
                float xk = row[k];
                const float4* w = (const float4*)(wl + k * WSTR);
                #pragma unroll
                for (int p = 0; p < 13; p++) {
                    float4 wv = w[p];
                    acc[4 * p]     = fmaf(xk, wv.x, acc[4 * p]);
                    acc[4 * p + 1] = fmaf(xk, wv.y, acc[4 * p + 1]);
                    acc[4 * p + 2] = fmaf(xk, wv.z, acc[4 * p + 2]);
                    acc[4 * p + 3] = fmaf(xk, wv.w, acc[4 * p + 3]);
                }
            }
            if (l < 3) {
                #pragma unroll
                for (int j = 0; j < HID; j++) row[j] = fmaxf(acc[j], 0.f);
            } else {
                #pragma unroll
                for (int j = 0; j < HID; j++) row[j] = acc[j];
            }
        }
    } else {
        #pragma unroll
        for (int j = 0; j < 52; j++) acc[j] = 0.f;
    }

    // BN stats: shuffle reduce -> smem float atomics -> global double atomics
    #pragma unroll 1
    for (int j = 0; j < HID; j++) {
        float v = acc[j];
        float s1 = v, q1 = v * v;
        #pragma unroll
        for (int o = 16; o; o >>= 1) {
            s1 += __shfl_xor_sync(0xffffffffu, s1, o);
            q1 += __shfl_xor_sync(0xffffffffu, q1, o);
        }
        if ((tid & 31) == 0) {
            atomicAdd(&s_sum[j], s1);
            atomicAdd(&s_sq[j], q1);
        }
    }
    __syncthreads();
    if (tid < HID) {
        atomicAdd(&g_sum[tid], (double)s_sum[tid]);
        atomicAdd(&g_sq[tid], (double)s_sq[tid]);
    }

    // write pre-BN x tile, coalesced
    for (int idx = tid; idx < cnt * HID; idx += 128) {
        int n = idx / 50, f = idx - n * 50;
        g_x[(size_t)base * HID + idx] = act[n * ASTR + f];
    }
}

__global__ void finalize_k(const float* __restrict__ gamma,
                           const float* __restrict__ beta, double invN) {
    int f = threadIdx.x;
    if (f >= HID) return;
    double mu = g_sum[f] * invN;
    double var = g_sq[f] * invN - mu * mu;
    float istd = (float)rsqrt(var + 1e-5);
    float sc = istd * gamma[f];
    g_scale[f] = sc;
    g_shift[f] = fmaf(-(float)mu, sc, beta[f]);
}

__global__ void out_k(float* __restrict__ dout, int NE) {
    int i = blockIdx.x * blockDim.x + threadIdx.x;
    if (i >= NE) return;
    int f = i % HID;
    dout[i] = fmaf(g_x[i], g_scale[f], g_shift[f]);
}

// ---------------- launch ----------------
extern "C" void kernel_launch(void* const* d_in, const int* in_sizes, int n_in,
                              void* d_out, int out_size) {
    const float* xy     = (const float*)d_in[0];
    const int*   seg    = (const int*)  d_in[1];
    const float* w_init = (const float*)d_in[3];
    const float* b_init = (const float*)d_in[4];
    const float* Ws1    = (const float*)d_in[5];
    const float* bs1    = (const float*)d_in[6];
    const float* Ws     = (const float*)d_in[7];
    const float* bs     = (const float*)d_in[8];
    const float* gamma  = (const float*)d_in[9];
    const float* beta   = (const float*)d_in[10];
    float* out = (float*)d_out;

    int N  = in_sizes[1];
    int NE = N * HID;

    const int smem_bytes = (5200 + 10400 + 52 + 208 + 152 + 52 + 52 + 128 + TILE * ASTR) * (int)sizeof(float);
    cudaFuncSetAttribute(mlp_k, cudaFuncAttributeMaxDynamicSharedMemorySize, smem_bytes);

    zero_cnt_k<<<(GCAP + 255) / 256, 256>>>();
    count_k<<<(N + 255) / 256, 256>>>(seg, N);
    invc_k<<<(GCAP + 255) / 256, 256>>>();

    for (int i = 0; i < 2; i++) {
        zero_stats_k<<<(GCAP * HID + 255) / 256, 256>>>();
        segsum_k<<<(N + 255) / 256, 64>>>(i, xy, seg, w_init, b_init, N);
        mlp_k<<<(N + TILE - 1) / TILE, TILE, smem_bytes>>>(
            i, xy, seg, w_init, b_init,
            Ws1 + i * (2 * HID * HID), bs1 + i * HID,
            Ws  + i * (4 * HID * HID), bs  + i * (4 * HID),
            N);
        finalize_k<<<1, 64>>>(gamma + i * HID, beta + i * HID, 1.0 / (double)N);
    }
    out_k<<<(NE + 255) / 256, 256>>>(out, NE);
}

// round 8
// speedup vs baseline: 2.3775x; 2.3775x over previous
#include <cuda_runtime.h>

#define HID 50
#define GCAP 16384
#define NMAX_ELEMS 50000000
#define ASTR 101
#define WSTR 52
#define TILE 256

// ---------------- scratch (device globals; no allocations) ----------------
__device__ float  g_x[NMAX_ELEMS];
__device__ float  g_mean[(size_t)GCAP * HID];
__device__ float  g_invc[GCAP];
__device__ int    g_cnt[GCAP];
__device__ double g_sum[64];
__device__ double g_sq[64];
__device__ float  g_scale[64];
__device__ float  g_shift[64];

// ---------------- small utility kernels ----------------
__global__ void zero_cnt_k() {
    int i = blockIdx.x * blockDim.x + threadIdx.x;
    if (i < GCAP) g_cnt[i] = 0;
}

__global__ void count_k(const int* __restrict__ seg, int N) {
    int i = blockIdx.x * blockDim.x + threadIdx.x;
    if (i < N) atomicAdd(&g_cnt[seg[i]], 1);
}

__global__ void invc_k() {
    int i = blockIdx.x * blockDim.x + threadIdx.x;
    if (i < GCAP) {
        int c = g_cnt[i];
        g_invc[i] = 1.0f / (float)(c > 1 ? c : 1);
    }
}

__global__ void zero_stats_k() {
    int i = blockIdx.x * blockDim.x + threadIdx.x;
    if (i < GCAP * HID) g_mean[i] = 0.f;
    if (i < 64) { g_sum[i] = 0.0; g_sq[i] = 0.0; }
}

// segment sum into g_mean; h computed on the fly.
// mode 0: h = xy @ w_init + b_init ; mode 1: h = g_x * scale + shift
__global__ void segsum_k(int mode, const float* __restrict__ xy,
                         const int* __restrict__ seg,
                         const float* __restrict__ WI, const float* __restrict__ BI,
                         int N) {
    __shared__ int ss[256];
    __shared__ float sxy[512];
    int base = blockIdx.x * 256;
    int cnt = N - base; if (cnt > 256) cnt = 256;
    if (cnt <= 0) return;
    for (int i = threadIdx.x; i < cnt; i += 64) ss[i] = seg[base + i];
    if (mode == 0)
        for (int i = threadIdx.x; i < 2 * cnt; i += 64) sxy[i] = xy[2 * base + i];
    __syncthreads();
    int f = threadIdx.x;
    if (f >= HID) return;
    float w0 = 0.f, w1 = 0.f, bf = 0.f, sc = 0.f, sh = 0.f;
    if (mode == 0) { w0 = WI[f]; w1 = WI[HID + f]; bf = BI[f]; }
    else           { sc = g_scale[f]; sh = g_shift[f]; }
    float acc = 0.f;
    int cur = ss[0];
    #pragma unroll 4
    for (int i = 0; i < cnt; i++) {
        float v;
        if (mode == 0) v = fmaf(sxy[2 * i], w0, fmaf(sxy[2 * i + 1], w1, bf));
        else           v = fmaf(g_x[(size_t)(base + i) * HID + f], sc, sh);
        int s = ss[i];
        if (s != cur) {
            atomicAdd(&g_mean[(size_t)cur * HID + f], acc);
            acc = 0.f; cur = s;
        }
        acc += v;
    }
    atomicAdd(&g_mean[(size_t)cur * HID + f], acc);
}

// ---------------- fused MLP + BN-stats kernel (float4 weight loads) ----------------
__global__ __launch_bounds__(256)
void mlp_k(int mode, const float* __restrict__ xy, const int* __restrict__ seg,
           const float* __restrict__ WI, const float* __restrict__ BI,
           const float* __restrict__ W1, const float* __restrict__ B1,
           const float* __restrict__ W2, const float* __restrict__ B2,
           int N) {
    extern __shared__ float sm[];
    float* s_w1  = sm;                     // 100 x 52 = 5200
    float* s_w   = s_w1 + 5200;            // 4 x 50 x 52 = 10400
    float* s_b1  = s_w + 10400;            // 52
    float* s_b2  = s_b1 + 52;              // 4 x 52 = 208
    float* s_wi  = s_b2 + 208;             // 152
    float* s_sum = s_wi + 152;             // 52
    float* s_sq  = s_sum + 52;             // 52
    int*   s_seg = (int*)(s_sq + 52);      // 256
    float* act   = (float*)(s_seg + 256);  // 256 x 101
    // total: 16372 + 25856 = 42228 floats = 168,912 B -> 1 block/SM, 8 warps

    int tid = threadIdx.x;
    // zero padded weight region (cols 50,51 of every 52-wide row must be 0)
    for (int i = tid; i < 15600; i += 256) sm[i] = 0.f;
    __syncthreads();
    for (int i = tid; i < 5000; i += 256)  { int r = i / 50, c = i - r * 50; s_w1[r * WSTR + c] = W1[i]; }
    for (int i = tid; i < 10000; i += 256) { int r = i / 50, c = i - r * 50; s_w[r * WSTR + c] = W2[i]; }
    if (tid < 52) s_b1[tid] = (tid < 50) ? B1[tid] : 0.f;
    for (int i = tid; i < 208; i += 256) { int l = i / 52, c = i - l * 52; s_b2[i] = (c < 50) ? B2[l * 50 + c] : 0.f; }
    for (int i = tid; i < 152; i += 256) s_wi[i] = (i < 100) ? WI[i] : ((i < 150) ? BI[i - 100] : 0.f);
    if (tid < 52) { s_sum[tid] = 0.f; s_sq[tid] = 0.f; }

    int base = blockIdx.x * TILE;
    int cnt = N - base; if (cnt > TILE) cnt = TILE;
    if (cnt < 0) cnt = 0;
    if (tid < cnt) s_seg[tid] = seg[base + tid];
    __syncthreads();

    // stage h into cols [50,100)
    for (int idx = tid; idx < cnt * HID; idx += 256) {
        int n = idx / 50, f = idx - n * 50;
        float hv;
        if (mode == 0) {
            float x0 = __ldg(&xy[2 * (base + n)]);
            float x1 = __ldg(&xy[2 * (base + n) + 1]);
            hv = fmaf(x0, s_wi[f], fmaf(x1, s_wi[50 + f], s_wi[100 + f]));
        } else {
            hv = fmaf(g_x[(size_t)base * HID + idx], g_scale[f], g_shift[f]);
        }
        act[n * ASTR + 50 + f] = hv;
    }
    // stage glob into cols [0,50) (thread-per-node; sorted ids -> L1 broadcast)
    if (tid < cnt) {
        int s = s_seg[tid];
        float ic = g_invc[s];
        const float* mrow = &g_mean[(size_t)s * HID];
        float* arow = act + tid * ASTR;
        #pragma unroll 1
        for (int f = 0; f < HID; f++) arow[f] = mrow[f] * ic;
    }
    __syncthreads();

    float acc[52];
    bool valid = tid < cnt;
    if (valid) {
        float* row = act + tid * ASTR;
        // layer 1: 100 -> 50, relu
        #pragma unroll
        for (int j = 0; j < 52; j++) acc[j] = s_b1[j];
        #pragma unroll 2
        for (int k = 0; k < 100; k++) {
            float xk = row[k];
            const float4* w = (const float4*)(s_w1 + k * WSTR);
            #pragma unroll
            for (int p = 0; p < 13; p++) {
                float4 wv = w[p];
                acc[4 * p]     = fmaf(xk, wv.x, acc[4 * p]);
                acc[4 * p + 1] = fmaf(xk, wv.y, acc[4 * p + 1]);
                acc[4 * p + 2] = fmaf(xk, wv.z, acc[4 * p + 2]);
                acc[4 * p + 3] = fmaf(xk, wv.w, acc[4 * p + 3]);
            }
        }
        #pragma unroll
        for (int j = 0; j < HID; j++) row[j] = fmaxf(acc[j], 0.f);
        // layers 2..5: 50 -> 50, relu on first 3
        #pragma unroll 1
        for (int l = 0; l < 4; l++) {
            const float* wl = s_w + l * 2600;
            const float* bl = s_b2 + l * 52;
            #pragma unroll
            for (int j = 0; j < 52; j++) acc[j] = bl[j];
            #pragma unroll 2
            for (int k = 0; k < 50; k++) {
                float xk = row[k];
                const float4* w = (const float4*)(wl + k * WSTR);
                #pragma unroll
                for (int p = 0; p < 13; p++) {
                    float4 wv = w[p];
                    acc[4 * p]     = fmaf(xk, wv.x, acc[4 * p]);
                    acc[4 * p + 1] = fmaf(xk, wv.y, acc[4 * p + 1]);
                    acc[4 * p + 2] = fmaf(xk, wv.z, acc[4 * p + 2]);
                    acc[4 * p + 3] = fmaf(xk, wv.w, acc[4 * p + 3]);
                }
            }
            if (l < 3) {
                #pragma unroll
                for (int j = 0; j < HID; j++) row[j] = fmaxf(acc[j], 0.f);
            } else {
                #pragma unroll
                for (int j = 0; j < HID; j++) row[j] = acc[j];
            }
        }
    } else {
        #pragma unroll
        for (int j = 0; j < 52; j++) acc[j] = 0.f;
    }

    // BN stats: shuffle reduce -> smem float atomics -> global double atomics
    #pragma unroll 1
    for (int j = 0; j < HID; j++) {
        float v = acc[j];
        float s1 = v, q1 = v * v;
        #pragma unroll
        for (int o = 16; o; o >>= 1) {
            s1 += __shfl_xor_sync(0xffffffffu, s1, o);
            q1 += __shfl_xor_sync(0xffffffffu, q1, o);
        }
        if ((tid & 31) == 0) {
            atomicAdd(&s_sum[j], s1);
            atomicAdd(&s_sq[j], q1);
        }
    }
    __syncthreads();
    if (tid < HID) {
        atomicAdd(&g_sum[tid], (double)s_sum[tid]);
        atomicAdd(&g_sq[tid], (double)s_sq[tid]);
    }

    // write pre-BN x tile, coalesced
    for (int idx = tid; idx < cnt * HID; idx += 256) {
        int n = idx / 50, f = idx - n * 50;
        g_x[(size_t)base * HID + idx] = act[n * ASTR + f];
    }
}

__global__ void finalize_k(const float* __restrict__ gamma,
                           const float* __restrict__ beta, double invN) {
    int f = threadIdx.x;
    if (f >= HID) return;
    double mu = g_sum[f] * invN;
    double var = g_sq[f] * invN - mu * mu;
    float istd = (float)rsqrt(var + 1e-5);
    float sc = istd * gamma[f];
    g_scale[f] = sc;
    g_shift[f] = fmaf(-(float)mu, sc, beta[f]);
}

__global__ void out_k(float* __restrict__ dout, int NE) {
    int i = blockIdx.x * blockDim.x + threadIdx.x;
    if (i >= NE) return;
    int f = i % HID;
    dout[i] = fmaf(g_x[i], g_scale[f], g_shift[f]);
}

// ---------------- launch ----------------
extern "C" void kernel_launch(void* const* d_in, const int* in_sizes, int n_in,
                              void* d_out, int out_size) {
    const float* xy     = (const float*)d_in[0];
    const int*   seg    = (const int*)  d_in[1];
    const float* w_init = (const float*)d_in[3];
    const float* b_init = (const float*)d_in[4];
    const float* Ws1    = (const float*)d_in[5];
    const float* bs1    = (const float*)d_in[6];
    const float* Ws     = (const float*)d_in[7];
    const float* bs     = (const float*)d_in[8];
    const float* gamma  = (const float*)d_in[9];
    const float* beta   = (const float*)d_in[10];
    float* out = (float*)d_out;

    int N  = in_sizes[1];
    int NE = N * HID;

    const int smem_bytes = (5200 + 10400 + 52 + 208 + 152 + 52 + 52 + 256 + TILE * ASTR) * (int)sizeof(float);
    cudaFuncSetAttribute(mlp_k, cudaFuncAttributeMaxDynamicSharedMemorySize, smem_bytes);

    zero_cnt_k<<<(GCAP + 255) / 256, 256>>>();
    count_k<<<(N + 255) / 256, 256>>>(seg, N);
    invc_k<<<(GCAP + 255) / 256, 256>>>();

    for (int i = 0; i < 2; i++) {
        zero_stats_k<<<(GCAP * HID + 255) / 256, 256>>>();
        segsum_k<<<(N + 255) / 256, 64>>>(i, xy, seg, w_init, b_init, N);
        mlp_k<<<(N + TILE - 1) / TILE, 256, smem_bytes>>>(
            i, xy, seg, w_init, b_init,
            Ws1 + i * (2 * HID * HID), bs1 + i * HID,
            Ws  + i * (4 * HID * HID), bs  + i * (4 * HID),
            N);
        finalize_k<<<1, 64>>>(gamma + i * HID, beta + i * HID, 1.0 / (double)N);
    }
    out_k<<<(NE + 255) / 256, 256>>>(out, NE);
}

// round 9
// speedup vs baseline: 2.5165x; 1.0585x over previous
#include <cuda_runtime.h>

#define HID 50
#define GCAP 16384
#define NMAX_ELEMS 50000000
#define ASTR 101
#define WSTR 52
#define TILE 384

// ---------------- scratch (device globals; no allocations) ----------------
__device__ float  g_x[NMAX_ELEMS];
__device__ float  g_mean[(size_t)GCAP * HID];
__device__ float  g_invc[GCAP];
__device__ int    g_cnt[GCAP];
__device__ double g_sum[64];
__device__ double g_sq[64];
__device__ float  g_scale[64];
__device__ float  g_shift[64];

// ---------------- small utility kernels ----------------
__global__ void zero_cnt_k() {
    int i = blockIdx.x * blockDim.x + threadIdx.x;
    if (i < GCAP) g_cnt[i] = 0;
}

__global__ void count_k(const int* __restrict__ seg, int N) {
    int i = blockIdx.x * blockDim.x + threadIdx.x;
    if (i < N) atomicAdd(&g_cnt[seg[i]], 1);
}

__global__ void invc_k() {
    int i = blockIdx.x * blockDim.x + threadIdx.x;
    if (i < GCAP) {
        int c = g_cnt[i];
        g_invc[i] = 1.0f / (float)(c > 1 ? c : 1);
    }
}

__global__ void zero_stats_k() {
    int i = blockIdx.x * blockDim.x + threadIdx.x;
    if (i < GCAP * HID) g_mean[i] = 0.f;
    if (i < 64) { g_sum[i] = 0.0; g_sq[i] = 0.0; }
}

// segment sum into g_mean; h computed on the fly.
// mode 0: h = xy @ w_init + b_init ; mode 1: h = g_x * scale + shift
__global__ void segsum_k(int mode, const float* __restrict__ xy,
                         const int* __restrict__ seg,
                         const float* __restrict__ WI, const float* __restrict__ BI,
                         int N) {
    __shared__ int ss[256];
    __shared__ float sxy[512];
    int base = blockIdx.x * 256;
    int cnt = N - base; if (cnt > 256) cnt = 256;
    if (cnt <= 0) return;
    for (int i = threadIdx.x; i < cnt; i += 64) ss[i] = seg[base + i];
    if (mode == 0)
        for (int i = threadIdx.x; i < 2 * cnt; i += 64) sxy[i] = xy[2 * base + i];
    __syncthreads();
    int f = threadIdx.x;
    if (f >= HID) return;
    float w0 = 0.f, w1 = 0.f, bf = 0.f, sc = 0.f, sh = 0.f;
    if (mode == 0) { w0 = WI[f]; w1 = WI[HID + f]; bf = BI[f]; }
    else           { sc = g_scale[f]; sh = g_shift[f]; }
    float acc = 0.f;
    int cur = ss[0];
    #pragma unroll 4
    for (int i = 0; i < cnt; i++) {
        float v;
        if (mode == 0) v = fmaf(sxy[2 * i], w0, fmaf(sxy[2 * i + 1], w1, bf));
        else           v = fmaf(g_x[(size_t)(base + i) * HID + f], sc, sh);
        int s = ss[i];
        if (s != cur) {
            atomicAdd(&g_mean[(size_t)cur * HID + f], acc);
            acc = 0.f; cur = s;
        }
        acc += v;
    }
    atomicAdd(&g_mean[(size_t)cur * HID + f], acc);
}

// ---------------- fused MLP + BN-stats kernel (float4 weight loads, 12 warps) ----------------
__global__ __launch_bounds__(384)
void mlp_k(int mode, const float* __restrict__ xy, const int* __restrict__ seg,
           const float* __restrict__ WI, const float* __restrict__ BI,
           const float* __restrict__ W1, const float* __restrict__ B1,
           const float* __restrict__ W2, const float* __restrict__ B2,
           int N) {
    extern __shared__ float sm[];
    float* s_w1  = sm;                     // 100 x 52 = 5200
    float* s_w   = s_w1 + 5200;            // 4 x 50 x 52 = 10400
    float* s_b1  = s_w + 10400;            // 52
    float* s_b2  = s_b1 + 52;              // 4 x 52 = 208
    float* s_wi  = s_b2 + 208;             // 152
    float* s_sum = s_wi + 152;             // 52
    float* s_sq  = s_sum + 52;             // 52
    int*   s_seg = (int*)(s_sq + 52);      // 384
    float* act   = (float*)(s_seg + 384);  // 384 x 101 = 38784
    // total: 16116 + 384 + 38784 = 55284 floats = 221,136 B -> 1 block/SM, 12 warps

    int tid = threadIdx.x;
    // zero padded weight region (cols 50,51 of every 52-wide row must be 0)
    for (int i = tid; i < 15600; i += TILE) sm[i] = 0.f;
    __syncthreads();
    for (int i = tid; i < 5000; i += TILE)  { int r = i / 50, c = i - r * 50; s_w1[r * WSTR + c] = W1[i]; }
    for (int i = tid; i < 10000; i += TILE) { int r = i / 50, c = i - r * 50; s_w[r * WSTR + c] = W2[i]; }
    if (tid < 52) s_b1[tid] = (tid < 50) ? B1[tid] : 0.f;
    for (int i = tid; i < 208; i += TILE) { int l = i / 52, c = i - l * 52; s_b2[i] = (c < 50) ? B2[l * 50 + c] : 0.f; }
    for (int i = tid; i < 152; i += TILE) s_wi[i] = (i < 100) ? WI[i] : ((i < 150) ? BI[i - 100] : 0.f);
    if (tid < 52) { s_sum[tid] = 0.f; s_sq[tid] = 0.f; }

    int base = blockIdx.x * TILE;
    int cnt = N - base; if (cnt > TILE) cnt = TILE;
    if (cnt < 0) cnt = 0;
    if (tid < cnt) s_seg[tid] = seg[base + tid];
    __syncthreads();

    // stage h into cols [50,100)
    for (int idx = tid; idx < cnt * HID; idx += TILE) {
        int n = idx / 50, f = idx - n * 50;
        float hv;
        if (mode == 0) {
            float x0 = __ldg(&xy[2 * (base + n)]);
            float x1 = __ldg(&xy[2 * (base + n) + 1]);
            hv = fmaf(x0, s_wi[f], fmaf(x1, s_wi[50 + f], s_wi[100 + f]));
        } else {
            hv = fmaf(g_x[(size_t)base * HID + idx], g_scale[f], g_shift[f]);
        }
        act[n * ASTR + 50 + f] = hv;
    }
    // stage glob into cols [0,50) (thread-per-node; sorted ids -> L1 broadcast)
    if (tid < cnt) {
        int s = s_seg[tid];
        float ic = g_invc[s];
        const float* mrow = &g_mean[(size_t)s * HID];
        float* arow = act + tid * ASTR;
        #pragma unroll 1
        for (int f = 0; f < HID; f++) arow[f] = mrow[f] * ic;
    }
    __syncthreads();

    float acc[52];
    bool valid = tid < cnt;
    if (valid) {
        float* row = act + tid * ASTR;
        // layer 1: 100 -> 50, relu
        #pragma unroll
        for (int j = 0; j < 52; j++) acc[j] = s_b1[j];
        #pragma unroll 2
        for (int k = 0; k < 100; k++) {
            float xk = row[k];
            const float4* w = (const float4*)(s_w1 + k * WSTR);
            #pragma unroll
            for (int p = 0; p < 13; p++) {
                float4 wv = w[p];
                acc[4 * p]     = fmaf(xk, wv.x, acc[4 * p]);
                acc[4 * p + 1] = fmaf(xk, wv.y, acc[4 * p + 1]);
                acc[4 * p + 2] = fmaf(xk, wv.z, acc[4 * p + 2]);
                acc[4 * p + 3] = fmaf(xk, wv.w, acc[4 * p + 3]);
            }
        }
        #pragma unroll
        for (int j = 0; j < HID; j++) row[j] = fmaxf(acc[j], 0.f);
        // layers 2..5: 50 -> 50, relu on first 3
        #pragma unroll 1
        for (int l = 0; l < 4; l++) {
            const float* wl = s_w + l * 2600;
            const float* bl = s_b2 + l * 52;
            #pragma unroll
            for (int j = 0; j < 52; j++) acc[j] = bl[j];
            #pragma unroll 2
            for (int k = 0; k < 50; k++) {
                float xk = row[k];
                const float4* w = (const float4*)(wl + k * WSTR);
                #pragma unroll
                for (int p = 0; p < 13; p++) {
                    float4 wv = w[p];
                    acc[4 * p]     = fmaf(xk, wv.x, acc[4 * p]);
                    acc[4 * p + 1] = fmaf(xk, wv.y, acc[4 * p + 1]);
                    acc[4 * p + 2] = fmaf(xk, wv.z, acc[4 * p + 2]);
                    acc[4 * p + 3] = fmaf(xk, wv.w, acc[4 * p + 3]);
                }
            }
            if (l < 3) {
                #pragma unroll
                for (int j = 0; j < HID; j++) row[j] = fmaxf(acc[j], 0.f);
            } else {
                #pragma unroll
                for (int j = 0; j < HID; j++) row[j] = acc[j];
            }
        }
    } else {
        #pragma unroll
        for (int j = 0; j < 52; j++) acc[j] = 0.f;
    }

    // BN stats: shuffle reduce -> smem float atomics -> global double atomics
    #pragma unroll 1
    for (int j = 0; j < HID; j++) {
        float v = acc[j];
        float s1 = v, q1 = v * v;
        #pragma unroll
        for (int o = 16; o; o >>= 1) {
            s1 += __shfl_xor_sync(0xffffffffu, s1, o);
            q1 += __shfl_xor_sync(0xffffffffu, q1, o);
        }
        if ((tid & 31) == 0) {
            atomicAdd(&s_sum[j], s1);
            atomicAdd(&s_sq[j], q1);
        }
    }
    __syncthreads();
    if (tid < HID) {
        atomicAdd(&g_sum[tid], (double)s_sum[tid]);
        atomicAdd(&g_sq[tid], (double)s_sq[tid]);
    }

    // write pre-BN x tile, coalesced
    for (int idx = tid; idx < cnt * HID; idx += TILE) {
        int n = idx / 50, f = idx - n * 50;
        g_x[(size_t)base * HID + idx] = act[n * ASTR + f];
    }
}

__global__ void finalize_k(const float* __restrict__ gamma,
                           const float* __restrict__ beta, double invN) {
    int f = threadIdx.x;
    if (f >= HID) return;
    double mu = g_sum[f] * invN;
    double var = g_sq[f] * invN - mu * mu;
    float istd = (float)rsqrt(var + 1e-5);
    float sc = istd * gamma[f];
    g_scale[f] = sc;
    g_shift[f] = fmaf(-(float)mu, sc, beta[f]);
}

__global__ void out_k(float* __restrict__ dout, int NE) {
    int i = blockIdx.x * blockDim.x + threadIdx.x;
    if (i >= NE) return;
    int f = i % HID;
    dout[i] = fmaf(g_x[i], g_scale[f], g_shift[f]);
}

// ---------------- launch ----------------
extern "C" void kernel_launch(void* const* d_in, const int* in_sizes, int n_in,
                              void* d_out, int out_size) {
    const float* xy     = (const float*)d_in[0];
    const int*   seg    = (const int*)  d_in[1];
    const float* w_init = (const float*)d_in[3];
    const float* b_init = (const float*)d_in[4];
    const float* Ws1    = (const float*)d_in[5];
    const float* bs1    = (const float*)d_in[6];
    const float* Ws     = (const float*)d_in[7];
    const float* bs     = (const float*)d_in[8];
    const float* gamma  = (const float*)d_in[9];
    const float* beta   = (const float*)d_in[10];
    float* out = (float*)d_out;

    int N  = in_sizes[1];
    int NE = N * HID;

    const int smem_bytes = (5200 + 10400 + 52 + 208 + 152 + 52 + 52 + TILE + TILE * ASTR) * (int)sizeof(float);
    cudaFuncSetAttribute(mlp_k, cudaFuncAttributeMaxDynamicSharedMemorySize, smem_bytes);

    zero_cnt_k<<<(GCAP + 255) / 256, 256>>>();
    count_k<<<(N + 255) / 256, 256>>>(seg, N);
    invc_k<<<(GCAP + 255) / 256, 256>>>();

    for (int i = 0; i < 2; i++) {
        zero_stats_k<<<(GCAP * HID + 255) / 256, 256>>>();
        segsum_k<<<(N + 255) / 256, 64>>>(i, xy, seg, w_init, b_init, N);
        mlp_k<<<(N + TILE - 1) / TILE, TILE, smem_bytes>>>(
            i, xy, seg, w_init, b_init,
            Ws1 + i * (2 * HID * HID), bs1 + i * HID,
            Ws  + i * (4 * HID * HID), bs  + i * (4 * HID),
            N);
        finalize_k<<<1, 64>>>(gamma + i * HID, beta + i * HID, 1.0 / (double)N);
    }
    out_k<<<(NE + 255) / 256, 256>>>(out, NE);
}

// round 12
// speedup vs baseline: 2.8103x; 1.1168x over previous
#include <cuda_runtime.h>

#define HID 50
#define GCAP 16384
#define NMAX_ELEMS 50000000
#define ASTR 101
#define WSTR 52
#define TILE 384

typedef unsigned long long u64;

// ---------------- scratch (device globals; no allocations) ----------------
__device__ float  g_x[NMAX_ELEMS];
__device__ float  g_mean[(size_t)GCAP * HID];
__device__ float  g_invc[GCAP];
__device__ int    g_cnt[GCAP];
__device__ double g_sum[64];
__device__ double g_sq[64];
__device__ float  g_scale[64];
__device__ float  g_shift[64];

// ---------------- f32x2 helpers (sm_103a packed fp32, per SASS_QUICKREF) ----------------
__device__ __forceinline__ u64 ffma2(u64 a, u64 b, u64 c) {
    u64 d; asm("fma.rn.f32x2 %0,%1,%2,%3;" : "=l"(d) : "l"(a), "l"(b), "l"(c));
    return d;
}
__device__ __forceinline__ u64 pack2(float x, float y) {
    u64 d; asm("mov.b64 %0,{%1,%2};" : "=l"(d) : "f"(x), "f"(y));
    return d;
}
__device__ __forceinline__ void unpack2(u64 v, float& x, float& y) {
    asm("mov.b64 {%0,%1},%2;" : "=f"(x), "=f"(y) : "l"(v));
}

// ---------------- small utility kernels ----------------
__global__ void zero_cnt_k() {
    int i = blockIdx.x * blockDim.x + threadIdx.x;
    if (i < GCAP) g_cnt[i] = 0;
}

__global__ void count_k(const int* __restrict__ seg, int N) {
    int i = blockIdx.x * blockDim.x + threadIdx.x;
    if (i < N) atomicAdd(&g_cnt[seg[i]], 1);
}

__global__ void invc_k() {
    int i = blockIdx.x * blockDim.x + threadIdx.x;
    if (i < GCAP) {
        int c = g_cnt[i];
        g_invc[i] = 1.0f / (float)(c > 1 ? c : 1);
    }
}

__global__ void zero_stats_k() {
    int i = blockIdx.x * blockDim.x + threadIdx.x;
    if (i < GCAP * HID) g_mean[i] = 0.f;
    if (i < 64) { g_sum[i] = 0.0; g_sq[i] = 0.0; }
}

// segment sum into g_mean; h computed on the fly.
// mode 0: h = xy @ w_init + b_init ; mode 1: h = g_x * scale + shift
__global__ void segsum_k(int mode, const float* __restrict__ xy,
                         const int* __restrict__ seg,
                         const float* __restrict__ WI, const float* __restrict__ BI,
                         int N) {
    __shared__ int ss[256];
    __shared__ float sxy[512];
    int base = blockIdx.x * 256;
    int cnt = N - base; if (cnt > 256) cnt = 256;
    if (cnt <= 0) return;
    for (int i = threadIdx.x; i < cnt; i += 64) ss[i] = seg[base + i];
    if (mode == 0)
        for (int i = threadIdx.x; i < 2 * cnt; i += 64) sxy[i] = xy[2 * base + i];
    __syncthreads();
    int f = threadIdx.x;
    if (f >= HID) return;
    float w0 = 0.f, w1 = 0.f, bf = 0.f, sc = 0.f, sh = 0.f;
    if (mode == 0) { w0 = WI[f]; w1 = WI[HID + f]; bf = BI[f]; }
    else           { sc = g_scale[f]; sh = g_shift[f]; }
    float acc = 0.f;
    int cur = ss[0];
    #pragma unroll 4
    for (int i = 0; i < cnt; i++) {
        float v;
        if (mode == 0) v = fmaf(sxy[2 * i], w0, fmaf(sxy[2 * i + 1], w1, bf));
        else           v = fmaf(g_x[(size_t)(base + i) * HID + f], sc, sh);
        int s = ss[i];
        if (s != cur) {
            atomicAdd(&g_mean[(size_t)cur * HID + f], acc);
            acc = 0.f; cur = s;
        }
        acc += v;
    }
    atomicAdd(&g_mean[(size_t)cur * HID + f], acc);
}

// ---------------- fused MLP + BN-stats kernel (f32x2 packed, 12 warps) ----------------
__global__ __launch_bounds__(384)
void mlp_k(int mode, const float* __restrict__ xy, const int* __restrict__ seg,
           const float* __restrict__ WI, const float* __restrict__ BI,
           const float* __restrict__ W1, const float* __restrict__ B1,
           const float* __restrict__ W2, const float* __restrict__ B2,
           int N) {
    extern __shared__ float sm[];
    float* s_w1  = sm;                     // 100 x 52 = 5200
    float* s_w   = s_w1 + 5200;            // 4 x 50 x 52 = 10400
    float* s_b1  = s_w + 10400;            // 52
    float* s_b2  = s_b1 + 52;              // 4 x 52 = 208
    float* s_wi  = s_b2 + 208;             // 152
    float* s_sum = s_wi + 152;             // 52
    float* s_sq  = s_sum + 52;             // 52
    int*   s_seg = (int*)(s_sq + 52);      // 384
    float* act   = (float*)(s_seg + 384);  // 384 x 101 = 38784
    // total: 16116 + 384 + 38784 = 55284 floats = 221,136 B -> 1 block/SM, 12 warps

    int tid = threadIdx.x;
    // zero padded weight region (cols 50,51 of every 52-wide row must be 0)
    for (int i = tid; i < 15600; i += TILE) sm[i] = 0.f;
    __syncthreads();
    for (int i = tid; i < 5000; i += TILE)  { int r = i / 50, c = i - r * 50; s_w1[r * WSTR + c] = W1[i]; }
    for (int i = tid; i < 10000; i += TILE) { int r = i / 50, c = i - r * 50; s_w[r * WSTR + c] = W2[i]; }
    if (tid < 52) s_b1[tid] = (tid < 50) ? B1[tid] : 0.f;
    for (int i = tid; i < 208; i += TILE) { int l = i / 52, c = i - l * 52; s_b2[i] = (c < 50) ? B2[l * 50 + c] : 0.f; }
    for (int i = tid; i < 152; i += TILE) s_wi[i] = (i < 100) ? WI[i] : ((i < 150) ? BI[i - 100] : 0.f);
    if (tid < 52) { s_sum[tid] = 0.f; s_sq[tid] = 0.f; }

    int base = blockIdx.x * TILE;
    int cnt = N - base; if (cnt > TILE) cnt = TILE;
    if (cnt < 0) cnt = 0;
    if (tid < cnt) s_seg[tid] = seg[base + tid];
    __syncthreads();

    // stage h into cols [50,100)
    for (int idx = tid; idx < cnt * HID; idx += TILE) {
        int n = idx / 50, f = idx - n * 50;
        float hv;
        if (mode == 0) {
            float x0 = __ldg(&xy[2 * (base + n)]);
            float x1 = __ldg(&xy[2 * (base + n) + 1]);
            hv = fmaf(x0, s_wi[f], fmaf(x1, s_wi[50 + f], s_wi[100 + f]));
        } else {
            hv = fmaf(g_x[(size_t)base * HID + idx], g_scale[f], g_shift[f]);
        }
        act[n * ASTR + 50 + f] = hv;
    }
    // stage glob into cols [0,50) (thread-per-node; sorted ids -> L1 broadcast)
    if (tid < cnt) {
        int s = s_seg[tid];
        float ic = g_invc[s];
        const float* mrow = &g_mean[(size_t)s * HID];
        float* arow = act + tid * ASTR;
        #pragma unroll 1
        for (int f = 0; f < HID; f++) arow[f] = mrow[f] * ic;
    }
    __syncthreads();

    u64 acc[26];
    bool valid = tid < cnt;
    if (valid) {
        float* row = act + tid * ASTR;
        // layer 1: 100 -> 50, relu
        #pragma unroll
        for (int p = 0; p < 26; p++) acc[p] = pack2(s_b1[2 * p], s_b1[2 * p + 1]);
        #pragma unroll 2
        for (int k = 0; k < 100; k++) {
            float xk = row[k];
            u64 xx = pack2(xk, xk);
            const ulonglong2* w = (const ulonglong2*)(s_w1 + k * WSTR);
            #pragma unroll
            for (int p = 0; p < 13; p++) {
                ulonglong2 wv = w[p];
                acc[2 * p]     = ffma2(wv.x, xx, acc[2 * p]);
                acc[2 * p + 1] = ffma2(wv.y, xx, acc[2 * p + 1]);
            }
        }
        #pragma unroll
        for (int p = 0; p < 25; p++) {
            float a0, a1; unpack2(acc[p], a0, a1);
            row[2 * p] = fmaxf(a0, 0.f); row[2 * p + 1] = fmaxf(a1, 0.f);
        }
        // layers 2..5: 50 -> 50, relu on first 3
        #pragma unroll 1
        for (int l = 0; l < 4; l++) {
            const float* wl = s_w + l * 2600;
            const float* bl = s_b2 + l * 52;
            #pragma unroll
            for (int p = 0; p < 26; p++) acc[p] = pack2(bl[2 * p], bl[2 * p + 1]);
            #pragma unroll 2
            for (int k = 0; k < 50; k++) {
                float xk = row[k];
                u64 xx = pack2(xk, xk);
                const ulonglong2* w = (const ulonglong2*)(wl + k * WSTR);
                #pragma unroll
                for (int p = 0; p < 13; p++) {
                    ulonglong2 wv = w[p];
                    acc[2 * p]     = ffma2(wv.x, xx, acc[2 * p]);
                    acc[2 * p + 1] = ffma2(wv.y, xx, acc[2 * p + 1]);
                }
            }
            if (l < 3) {
                #pragma unroll
                for (int p = 0; p < 25; p++) {
                    float a0, a1; unpack2(acc[p], a0, a1);
                    row[2 * p] = fmaxf(a0, 0.f); row[2 * p + 1] = fmaxf(a1, 0.f);
                }
            } else {
                #pragma unroll
                for (int p = 0; p < 25; p++) {
                    float a0, a1; unpack2(acc[p], a0, a1);
                    row[2 * p] = a0; row[2 * p + 1] = a1;
                }
            }
        }
    } else {
        #pragma unroll
        for (int p = 0; p < 26; p++) acc[p] = 0ull;
    }

    // BN stats: shuffle reduce -> smem float atomics -> global double atomics
    #pragma unroll 1
    for (int p = 0; p < 25; p++) {
        float a0, a1; unpack2(acc[p], a0, a1);
        float s1 = a0, q1 = a0 * a0, s2 = a1, q2 = a1 * a1;
        #pragma unroll
        for (int o = 16; o; o >>= 1) {
            s1 += __shfl_xor_sync(0xffffffffu, s1, o);
            q1 += __shfl_xor_sync(0xffffffffu, q1, o);
            s2 += __shfl_xor_sync(0xffffffffu, s2, o);
            q2 += __shfl_xor_sync(0xffffffffu, q2, o);
        }
        if ((tid & 31) == 0) {
            atomicAdd(&s_sum[2 * p], s1);     atomicAdd(&s_sq[2 * p], q1);
            atomicAdd(&s_sum[2 * p + 1], s2); atomicAdd(&s_sq[2 * p + 1], q2);
        }
    }
    __syncthreads();
    if (tid < HID) {
        atomicAdd(&g_sum[tid], (double)s_sum[tid]);
        atomicAdd(&g_sq[tid], (double)s_sq[tid]);
    }

    // write pre-BN x tile, coalesced
    for (int idx = tid; idx < cnt * HID; idx += TILE) {
        int n = idx / 50, f = idx - n * 50;
        g_x[(size_t)base * HID + idx] = act[n * ASTR + f];
    }
}

__global__ void finalize_k(const float* __restrict__ gamma,
                           const float* __restrict__ beta, double invN) {
    int f = threadIdx.x;
    if (f >= HID) return;
    double mu = g_sum[f] * invN;
    double var = g_sq[f] * invN - mu * mu;
    float istd = (float)rsqrt(var + 1e-5);
    float sc = istd * gamma[f];
    g_scale[f] = sc;
    g_shift[f] = fmaf(-(float)mu, sc, beta[f]);
}

__global__ void out_k(float* __restrict__ dout, int NE) {
    int i = blockIdx.x * blockDim.x + threadIdx.x;
    if (i >= NE) return;
    int f = i % HID;
    dout[i] = fmaf(g_x[i], g_scale[f], g_shift[f]);
}

// ---------------- launch ----------------
extern "C" void kernel_launch(void* const* d_in, const int* in_sizes, int n_in,
                              void* d_out, int out_size) {
    const float* xy     = (const float*)d_in[0];
    const int*   seg    = (const int*)  d_in[1];
    const float* w_init = (const float*)d_in[3];
    const float* b_init = (const float*)d_in[4];
    const float* Ws1    = (const float*)d_in[5];
    const float* bs1    = (const float*)d_in[6];
    const float* Ws     = (const float*)d_in[7];
    const float* bs     = (const float*)d_in[8];
    const float* gamma  = (const float*)d_in[9];
    const float* beta   = (const float*)d_in[10];
    float* out = (float*)d_out;

    int N  = in_sizes[1];
    int NE = N * HID;

    const int smem_bytes = (5200 + 10400 + 52 + 208 + 152 + 52 + 52 + TILE + TILE * ASTR) * (int)sizeof(float);
    cudaFuncSetAttribute(mlp_k, cudaFuncAttributeMaxDynamicSharedMemorySize, smem_bytes);

    zero_cnt_k<<<(GCAP + 255) / 256, 256>>>();
    count_k<<<(N + 255) / 256, 256>>>(seg, N);
    invc_k<<<(GCAP + 255) / 256, 256>>>();

    for (int i = 0; i < 2; i++) {
        zero_stats_k<<<(GCAP * HID + 255) / 256, 256>>>();
        segsum_k<<<(N + 255) / 256, 64>>>(i, xy, seg, w_init, b_init, N);
        mlp_k<<<(N + TILE - 1) / TILE, TILE, smem_bytes>>>(
            i, xy, seg, w_init, b_init,
            Ws1 + i * (2 * HID * HID), bs1 + i * HID,
            Ws  + i * (4 * HID * HID), bs  + i * (4 * HID),
            N);
        finalize_k<<<1, 64>>>(gamma + i * HID, beta + i * HID, 1.0 / (double)N);
    }
    out_k<<<(NE + 255) / 256, 256>>>(out, NE);
}

// round 14
// speedup vs baseline: 2.9534x; 1.0509x over previous
#include <cuda_runtime.h>

#define HID 50
#define GCAP 16384
#define NMAX_ELEMS 50000000
#define ASTR 51
#define WSTR 52
#define TILE 512

typedef unsigned long long u64;

// ---------------- scratch (device globals; no allocations) ----------------
__device__ float  g_x[NMAX_ELEMS];
__device__ float  g_mean[(size_t)GCAP * HID];
__device__ float  g_invc[GCAP];
__device__ int    g_cnt[GCAP];
__device__ double g_sum[64];
__device__ double g_sq[64];
__device__ float  g_scale[64];
__device__ float  g_shift[64];

// ---------------- f32x2 helpers ----------------
__device__ __forceinline__ u64 ffma2(u64 a, u64 b, u64 c) {
    u64 d; asm("fma.rn.f32x2 %0,%1,%2,%3;" : "=l"(d) : "l"(a), "l"(b), "l"(c));
    return d;
}
__device__ __forceinline__ u64 pack2(float x, float y) {
    u64 d; asm("mov.b64 %0,{%1,%2};" : "=l"(d) : "f"(x), "f"(y));
    return d;
}
__device__ __forceinline__ void unpack2(u64 v, float& x, float& y) {
    asm("mov.b64 {%0,%1},%2;" : "=f"(x), "=f"(y) : "l"(v));
}

// ---------------- small utility kernels ----------------
__global__ void zero_cnt_k() {
    int i = blockIdx.x * blockDim.x + threadIdx.x;
    if (i < GCAP) g_cnt[i] = 0;
}

__global__ void count_k(const int* __restrict__ seg, int N) {
    int i = blockIdx.x * blockDim.x + threadIdx.x;
    if (i < N) atomicAdd(&g_cnt[seg[i]], 1);
}

__global__ void invc_k() {
    int i = blockIdx.x * blockDim.x + threadIdx.x;
    if (i < GCAP) {
        int c = g_cnt[i];
        g_invc[i] = 1.0f / (float)(c > 1 ? c : 1);
    }
}

__global__ void zero_stats_k() {
    int i = blockIdx.x * blockDim.x + threadIdx.x;
    if (i < GCAP * HID) g_mean[i] = 0.f;
    if (i < 64) { g_sum[i] = 0.0; g_sq[i] = 0.0; }
}

// g_mean := g_mean * invc  (turn sums into means once per iteration)
__global__ void scale_mean_k() {
    int i = blockIdx.x * blockDim.x + threadIdx.x;
    if (i < GCAP * HID) g_mean[i] *= g_invc[i / HID];
}

// segment sum into g_mean; h computed on the fly.
// mode 0: h = xy @ w_init + b_init ; mode 1: h = g_x * scale + shift
__global__ void segsum_k(int mode, const float* __restrict__ xy,
                         const int* __restrict__ seg,
                         const float* __restrict__ WI, const float* __restrict__ BI,
                         int N) {
    __shared__ int ss[256];
    __shared__ float sxy[512];
    int base = blockIdx.x * 256;
    int cnt = N - base; if (cnt > 256) cnt = 256;
    if (cnt <= 0) return;
    for (int i = threadIdx.x; i < cnt; i += 64) ss[i] = seg[base + i];
    if (mode == 0)
        for (int i = threadIdx.x; i < 2 * cnt; i += 64) sxy[i] = xy[2 * base + i];
    __syncthreads();
    int f = threadIdx.x;
    if (f >= HID) return;
    float w0 = 0.f, w1 = 0.f, bf = 0.f, sc = 0.f, sh = 0.f;
    if (mode == 0) { w0 = WI[f]; w1 = WI[HID + f]; bf = BI[f]; }
    else           { sc = g_scale[f]; sh = g_shift[f]; }
    float acc = 0.f;
    int cur = ss[0];
    #pragma unroll 4
    for (int i = 0; i < cnt; i++) {
        float v;
        if (mode == 0) v = fmaf(sxy[2 * i], w0, fmaf(sxy[2 * i + 1], w1, bf));
        else           v = fmaf(g_x[(size_t)(base + i) * HID + f], sc, sh);
        int s = ss[i];
        if (s != cur) {
            atomicAdd(&g_mean[(size_t)cur * HID + f], acc);
            acc = 0.f; cur = s;
        }
        acc += v;
    }
    atomicAdd(&g_mean[(size_t)cur * HID + f], acc);
}

// ---------------- fused MLP + BN-stats kernel (f32x2, 16 warps, slim act) ----------------
__global__ __launch_bounds__(512)
void mlp_k(int mode, const float* __restrict__ xy, const int* __restrict__ seg,
           const float* __restrict__ WI, const float* __restrict__ BI,
           const float* __restrict__ W1, const float* __restrict__ B1,
           const float* __restrict__ W2, const float* __restrict__ B2,
           int N) {
    extern __shared__ float sm[];
    float* s_w1  = sm;                     // 100 x 52 = 5200
    float* s_w   = s_w1 + 5200;            // 4 x 50 x 52 = 10400
    float* s_b1  = s_w + 10400;            // 52
    float* s_b2  = s_b1 + 52;              // 4 x 52 = 208
    float* s_wi  = s_b2 + 208;             // 152
    float* s_sum = s_wi + 152;             // 52
    float* s_sq  = s_sum + 52;             // 52
    int*   s_seg = (int*)(s_sq + 52);      // 512
    float* act   = (float*)(s_seg + 512);  // 512 x 51 = 26112
    // total: 16116 + 512 + 26112 = 42740 floats = 170,960 B -> 1 block/SM, 16 warps

    int tid = threadIdx.x;
    // zero padded weight region (cols 50,51 of every 52-wide row must be 0)
    for (int i = tid; i < 15600; i += TILE) sm[i] = 0.f;
    __syncthreads();
    for (int i = tid; i < 5000; i += TILE)  { int r = i / 50, c = i - r * 50; s_w1[r * WSTR + c] = W1[i]; }
    for (int i = tid; i < 10000; i += TILE) { int r = i / 50, c = i - r * 50; s_w[r * WSTR + c] = W2[i]; }
    if (tid < 52) s_b1[tid] = (tid < 50) ? B1[tid] : 0.f;
    for (int i = tid; i < 208; i += TILE) { int l = i / 52, c = i - l * 52; s_b2[i] = (c < 50) ? B2[l * 50 + c] : 0.f; }
    for (int i = tid; i < 152; i += TILE) s_wi[i] = (i < 100) ? WI[i] : ((i < 150) ? BI[i - 100] : 0.f);
    if (tid < 52) { s_sum[tid] = 0.f; s_sq[tid] = 0.f; }

    int base = blockIdx.x * TILE;
    int cnt = N - base; if (cnt > TILE) cnt = TILE;
    if (cnt < 0) cnt = 0;
    if (tid < cnt) s_seg[tid] = seg[base + tid];
    __syncthreads();

    // stage h into act (50-wide rows)
    for (int idx = tid; idx < cnt * HID; idx += TILE) {
        int n = idx / 50, f = idx - n * 50;
        float hv;
        if (mode == 0) {
            float x0 = __ldg(&xy[2 * (base + n)]);
            float x1 = __ldg(&xy[2 * (base + n) + 1]);
            hv = fmaf(x0, s_wi[f], fmaf(x1, s_wi[50 + f], s_wi[100 + f]));
        } else {
            hv = fmaf(g_x[(size_t)base * HID + idx], g_scale[f], g_shift[f]);
        }
        act[n * ASTR + f] = hv;
    }
    __syncthreads();

    u64 acc[26];
    bool valid = tid < cnt;
    if (valid) {
        float* row = act + tid * ASTR;
        const float* mrow = &g_mean[(size_t)s_seg[tid] * HID];
        // layer 1: 100 -> 50, relu.  k=0..49: glob (prescaled mean, L1 broadcast); k=50..99: h
        #pragma unroll
        for (int p = 0; p < 26; p++) acc[p] = pack2(s_b1[2 * p], s_b1[2 * p + 1]);
        #pragma unroll 2
        for (int k = 0; k < 50; k++) {
            float xk = __ldg(mrow + k);
            u64 xx = pack2(xk, xk);
            const ulonglong2* w = (const ulonglong2*)(s_w1 + k * WSTR);
            #pragma unroll
            for (int p = 0; p < 13; p++) {
                ulonglong2 wv = w[p];
                acc[2 * p]     = ffma2(wv.x, xx, acc[2 * p]);
                acc[2 * p + 1] = ffma2(wv.y, xx, acc[2 * p + 1]);
            }
        }
        #pragma unroll 2
        for (int k = 0; k < 50; k++) {
            float xk = row[k];
            u64 xx = pack2(xk, xk);
            const ulonglong2* w = (const ulonglong2*)(s_w1 + (50 + k) * WSTR);
            #pragma unroll
            for (int p = 0; p < 13; p++) {
                ulonglong2 wv = w[p];
                acc[2 * p]     = ffma2(wv.x, xx, acc[2 * p]);
                acc[2 * p + 1] = ffma2(wv.y, xx, acc[2 * p + 1]);
            }
        }
        #pragma unroll
        for (int p = 0; p < 25; p++) {
            float a0, a1; unpack2(acc[p], a0, a1);
            row[2 * p] = fmaxf(a0, 0.f); row[2 * p + 1] = fmaxf(a1, 0.f);
        }
        // layers 2..5: 50 -> 50, relu on first 3
        #pragma unroll 1
        for (int l = 0; l < 4; l++) {
            const float* wl = s_w + l * 2600;
            const float* bl = s_b2 + l * 52;
            #pragma unroll
            for (int p = 0; p < 26; p++) acc[p] = pack2(bl[2 * p], bl[2 * p + 1]);
            #pragma unroll 2
            for (int k = 0; k < 50; k++) {
                float xk = row[k];
                u64 xx = pack2(xk, xk);
                const ulonglong2* w = (const ulonglong2*)(wl + k * WSTR);
                #pragma unroll
                for (int p = 0; p < 13; p++) {
                    ulonglong2 wv = w[p];
                    acc[2 * p]     = ffma2(wv.x, xx, acc[2 * p]);
                    acc[2 * p + 1] = ffma2(wv.y, xx, acc[2 * p + 1]);
                }
            }
            if (l < 3) {
                #pragma unroll
                for (int p = 0; p < 25; p++) {
                    float a0, a1; unpack2(acc[p], a0, a1);
                    row[2 * p] = fmaxf(a0, 0.f); row[2 * p + 1] = fmaxf(a1, 0.f);
                }
            } else {
                #pragma unroll
                for (int p = 0; p < 25; p++) {
                    float a0, a1; unpack2(acc[p], a0, a1);
                    row[2 * p] = a0; row[2 * p + 1] = a1;
                }
            }
        }
    } else {
        #pragma unroll
        for (int p = 0; p < 26; p++) acc[p] = 0ull;
    }

    // BN stats: shuffle reduce -> smem float atomics -> global double atomics
    #pragma unroll 1
    for (int p = 0; p < 25; p++) {
        float a0, a1; unpack2(acc[p], a0, a1);
        float s1 = a0, q1 = a0 * a0, s2 = a1, q2 = a1 * a1;
        #pragma unroll
        for (int o = 16; o; o >>= 1) {
            s1 += __shfl_xor_sync(0xffffffffu, s1, o);
            q1 += __shfl_xor_sync(0xffffffffu, q1, o);
            s2 += __shfl_xor_sync(0xffffffffu, s2, o);
            q2 += __shfl_xor_sync(0xffffffffu, q2, o);
        }
        if ((tid & 31) == 0) {
            atomicAdd(&s_sum[2 * p], s1);     atomicAdd(&s_sq[2 * p], q1);
            atomicAdd(&s_sum[2 * p + 1], s2); atomicAdd(&s_sq[2 * p + 1], q2);
        }
    }
    __syncthreads();
    if (tid < HID) {
        atomicAdd(&g_sum[tid], (double)s_sum[tid]);
        atomicAdd(&g_sq[tid], (double)s_sq[tid]);
    }

    // write pre-BN x tile, coalesced
    for (int idx = tid; idx < cnt * HID; idx += TILE) {
        int n = idx / 50, f = idx - n * 50;
        g_x[(size_t)base * HID + idx] = act[n * ASTR + f];
    }
}

__global__ void finalize_k(const float* __restrict__ gamma,
                           const float* __restrict__ beta, double invN) {
    int f = threadIdx.x;
    if (f >= HID) return;
    double mu = g_sum[f] * invN;
    double var = g_sq[f] * invN - mu * mu;
    float istd = (float)rsqrt(var + 1e-5);
    float sc = istd * gamma[f];
    g_scale[f] = sc;
    g_shift[f] = fmaf(-(float)mu, sc, beta[f]);
}

__global__ void out_k(float* __restrict__ dout, int NE) {
    int i = blockIdx.x * blockDim.x + threadIdx.x;
    if (i >= NE) return;
    int f = i % HID;
    dout[i] = fmaf(g_x[i], g_scale[f], g_shift[f]);
}

// ---------------- launch ----------------
extern "C" void kernel_launch(void* const* d_in, const int* in_sizes, int n_in,
                              void* d_out, int out_size) {
    const float* xy     = (const float*)d_in[0];
    const int*   seg    = (const int*)  d_in[1];
    const float* w_init = (const float*)d_in[3];
    const float* b_init = (const float*)d_in[4];
    const float* Ws1    = (const float*)d_in[5];
    const float* bs1    = (const float*)d_in[6];
    const float* Ws     = (const float*)d_in[7];
    const float* bs     = (const float*)d_in[8];
    const float* gamma  = (const float*)d_in[9];
    const float* beta   = (const float*)d_in[10];
    float* out = (float*)d_out;

    int N  = in_sizes[1];
    int NE = N * HID;

    const int smem_bytes = (5200 + 10400 + 52 + 208 + 152 + 52 + 52 + TILE + TILE * ASTR) * (int)sizeof(float);
    cudaFuncSetAttribute(mlp_k, cudaFuncAttributeMaxDynamicSharedMemorySize, smem_bytes);

    zero_cnt_k<<<(GCAP + 255) / 256, 256>>>();
    count_k<<<(N + 255) / 256, 256>>>(seg, N);
    invc_k<<<(GCAP + 255) / 256, 256>>>();

    for (int i = 0; i < 2; i++) {
        zero_stats_k<<<(GCAP * HID + 255) / 256, 256>>>();
        segsum_k<<<(N + 255) / 256, 64>>>(i, xy, seg, w_init, b_init, N);
        scale_mean_k<<<(GCAP * HID + 255) / 256, 256>>>();
        mlp_k<<<(N + TILE - 1) / TILE, TILE, smem_bytes>>>(
            i, xy, seg, w_init, b_init,
            Ws1 + i * (2 * HID * HID), bs1 + i * HID,
            Ws  + i * (4 * HID * HID), bs  + i * (4 * HID),
            N);
        finalize_k<<<1, 64>>>(gamma + i * HID, beta + i * HID, 1.0 / (double)N);
    }
    out_k<<<(NE + 255) / 256, 256>>>(out, NE);
}